// round 7
// baseline (speedup 1.0000x reference)
#include <cuda_runtime.h>
#include <cuda_bf16.h>

// AngleTensor: out[b,i,j,k] = mask * acos( u_j . u_k ), u_t = (p_t-p_i)/|p_t-p_i|
// Issue-bound. R6 = R5 (packed f32x2 math) + signed-zero fix: the acos reflect
// offsets are pre-masked per-lane (hp_k = w_k*pi/2), so masked entries yield
// exactly 0 even when the packed dot product is -0.

#define AT_N 128
typedef unsigned long long u64;

__device__ __forceinline__ u64 pk(float lo, float hi) {
    u64 r; asm("mov.b64 %0, {%1, %2};" : "=l"(r) : "f"(lo), "f"(hi)); return r;
}
__device__ __forceinline__ float2 upk(u64 a) {
    float2 r; asm("mov.b64 {%0, %1}, %2;" : "=f"(r.x), "=f"(r.y) : "l"(a)); return r;
}
__device__ __forceinline__ u64 fma2(u64 a, u64 b, u64 c) {
    u64 d; asm("fma.rn.f32x2 %0, %1, %2, %3;" : "=l"(d) : "l"(a), "l"(b), "l"(c)); return d;
}
__device__ __forceinline__ u64 mul2(u64 a, u64 b) {
    u64 d; asm("mul.rn.f32x2 %0, %1, %2;" : "=l"(d) : "l"(a), "l"(b)); return d;
}
__device__ __forceinline__ float sqapx(float x) {
    float s; asm("sqrt.approx.f32 %0, %1;" : "=f"(s) : "f"(x)); return s;
}

__global__ __launch_bounds__(256)
void AngleTensor_69767448756825_kernel(const float* __restrict__ pos,
                                       float* __restrict__ out) {
    const int i    = blockIdx.x;
    const int b    = blockIdx.y;
    const int t    = threadIdx.x;
    const int lane = t & 31;
    const int w    = t >> 5;

    __shared__ float4 su[AT_N];                       // per-k: {x,y,z,w}
    __shared__ __align__(16) u64 su2[AT_N][4];        // per-j: {x,x},{y,y},{z,z},{w,w}

    const float* pb = pos + (size_t)b * AT_N * 3;
    const float pix = pb[i * 3 + 0];
    const float piy = pb[i * 3 + 1];
    const float piz = pb[i * 3 + 2];

    if (t < AT_N) {
        float dx = pb[t * 3 + 0] - pix;
        float dy = pb[t * 3 + 1] - piy;
        float dz = pb[t * 3 + 2] - piz;
        float n2 = dx * dx + dy * dy + dz * dz;
        float inv = (n2 > 0.0f) ? rsqrtf(n2) : 0.0f;  // t==i -> zero vector
        float wt  = (t == i) ? 0.0f : 1.0f;
        float x = dx * inv, y = dy * inv, z = dz * inv;
        su[t] = make_float4(x, y, z, wt);
        su2[t][0] = pk(x, x);
        su2[t][1] = pk(y, y);
        su2[t][2] = pk(z, z);
        su2[t][3] = pk(wt, wt);
    }
    __syncthreads();

    // Lane-owned k-quad packs.
    const int k0 = lane << 2;
    const float4 q0 = su[k0 + 0];
    const float4 q1 = su[k0 + 1];
    const float4 q2 = su[k0 + 2];
    const float4 q3 = su[k0 + 3];
    const u64 kx01 = pk(q0.x, q1.x), kx23 = pk(q2.x, q3.x);
    const u64 ky01 = pk(q0.y, q1.y), ky23 = pk(q2.y, q3.y);
    const u64 kz01 = pk(q0.z, q1.z), kz23 = pk(q2.z, q3.z);
    const u64 w01  = pk( q0.w,  q1.w), w23  = pk( q2.w,  q3.w);
    const u64 nw01 = pk(-q0.w, -q1.w), nw23 = pk(-q2.w, -q3.w);

    const float HPI = 1.57079632679f;
    // Pre-masked reflect offsets: +-pi/2 * w_k (0 on masked k -> r==0 even if c==-0)
    const u64 hp01  = pk( HPI * q0.w,  HPI * q1.w), hp23  = pk( HPI * q2.w,  HPI * q3.w);
    const u64 nhp01 = pk(-HPI * q0.w, -HPI * q1.w), nhp23 = pk(-HPI * q2.w, -HPI * q3.w);

    const u64 ABSM = 0x7fffffff7fffffffull;
    const u64 SGNB = 0x8000000080000000ull;
    const u64 ONEF = 0x3f8000003f800000ull;
    const u64 A3 = pk(-0.0187293f, -0.0187293f);
    const u64 A2 = pk( 0.0742610f,  0.0742610f);
    const u64 A1 = pk(-0.2121144f, -0.2121144f);
    const u64 A0 = pk( 1.5707288f,  1.5707288f);

    float4* orow = reinterpret_cast<float4*>(
        out + ((size_t)b * AT_N + i) * AT_N * AT_N);

    #pragma unroll 4
    for (int it = 0; it < AT_N / 8; ++it) {
        const int j = w * (AT_N / 8) + it;
        // Two broadcast LDS.128: {jx2, jy2} and {jz2, jw2}.
        const ulonglong2 a0 = reinterpret_cast<const ulonglong2*>(su2[j])[0];
        const ulonglong2 a1 = reinterpret_cast<const ulonglong2*>(su2[j])[1];
        const u64 jx = a0.x, jy = a0.y, jz = a1.x, jw = a1.y;

        // cos = u_j . u_k  (packed)
        u64 c01 = fma2(jz, kz01, fma2(jy, ky01, mul2(jx, kx01)));
        u64 c23 = fma2(jz, kz23, fma2(jy, ky23, mul2(jx, kx23)));

        // ax = |c|; y = w_k*(1-ax)  (k-mask folded); |y| guards diag rounding
        u64 ax01 = c01 & ABSM, ax23 = c23 & ABSM;
        u64 y01 = fma2(ax01, nw01, w01) & ABSM;
        u64 y23 = fma2(ax23, nw23, w23) & ABSM;
        float2 f01 = upk(y01), f23 = upk(y23);
        u64 s01 = pk(sqapx(f01.x), sqapx(f01.y));
        u64 s23 = pk(sqapx(f23.x), sqapx(f23.y));

        // poly(ax), A&S 4.4.45 (abs err <= 6.7e-5)
        u64 p01 = fma2(fma2(fma2(A3, ax01, A2), ax01, A1), ax01, A0);
        u64 p23 = fma2(fma2(fma2(A3, ax23, A2), ax23, A1), ax23, A0);

        // reflect with PRE-MASKED offsets: r = sg*(s*p - w_k*pi/2) + w_k*pi/2
        u64 sg01 = (c01 & SGNB) | ONEF;
        u64 sg23 = (c23 & SGNB) | ONEF;
        u64 r01 = fma2(sg01, fma2(s01, p01, nhp01), hp01);
        u64 r23 = fma2(sg23, fma2(s23, p23, nhp23), hp23);

        // j-mask (j==i row -> exact zeros)
        r01 = mul2(r01, jw);
        r23 = mul2(r23, jw);

        float2 g01 = upk(r01), g23 = upk(r23);
        float4 r4 = make_float4(g01.x, g01.y, g23.x, g23.y);

        // exact zero on the j==k diagonal
        if ((j >> 2) == lane) {
            switch (j & 3) {
                case 0: r4.x = 0.0f; break;
                case 1: r4.y = 0.0f; break;
                case 2: r4.z = 0.0f; break;
                default: r4.w = 0.0f; break;
            }
        }

        orow[j * (AT_N / 4) + lane] = r4;             // STG.128 coalesced
    }
}

extern "C" void kernel_launch(void* const* d_in, const int* in_sizes, int n_in,
                              void* d_out, int out_size) {
    const int B = out_size / (AT_N * AT_N * AT_N);

    const float* pos = nullptr;
    for (int a = 0; a < n_in; ++a)
        if (in_sizes[a] == B * AT_N * 3) pos = (const float*)d_in[a];
    if (!pos) pos = (const float*)d_in[0];

    dim3 grid(AT_N, B);
    AngleTensor_69767448756825_kernel<<<grid, 256>>>(pos, (float*)d_out);
}

// round 8
// speedup vs baseline: 1.0172x; 1.0172x over previous
#include <cuda_runtime.h>
#include <cuda_bf16.h>

// AngleTensor: out[b,i,j,k] = mask * acos( u_j . u_k ), u_t = (p_t-p_i)/|p_t-p_i|
// Issue/occupancy-bound. R7 hybrid: f32x2 packed dot product (reused k-packs),
// scalar epilogue exploiting free |x|/-x operand modifiers and immediate
// constants -> ~24 const regs instead of ~46, ~53 warp-instrs/row.

#define AT_N 128
typedef unsigned long long u64;

__device__ __forceinline__ u64 pk(float lo, float hi) {
    u64 r; asm("mov.b64 %0, {%1, %2};" : "=l"(r) : "f"(lo), "f"(hi)); return r;
}
__device__ __forceinline__ float2 upk(u64 a) {
    float2 r; asm("mov.b64 {%0, %1}, %2;" : "=f"(r.x), "=f"(r.y) : "l"(a)); return r;
}
__device__ __forceinline__ u64 fma2(u64 a, u64 b, u64 c) {
    u64 d; asm("fma.rn.f32x2 %0, %1, %2, %3;" : "=l"(d) : "l"(a), "l"(b), "l"(c)); return d;
}
__device__ __forceinline__ u64 mul2(u64 a, u64 b) {
    u64 d; asm("mul.rn.f32x2 %0, %1, %2;" : "=l"(d) : "l"(a), "l"(b)); return d;
}
__device__ __forceinline__ float sqapx(float x) {
    float s; asm("sqrt.approx.f32 %0, %1;" : "=f"(s) : "f"(x)); return s;
}

// Scalar acos epilogue. w = k-mask (0/1), nhp = -pi/2 * w (pre-masked offset:
// masked k yields exactly 0 even when the packed dot produced c = -0).
// |c| and -nhp fold into FFMA operand modifiers (free).
__device__ __forceinline__ float ang(float c, float w, float nhp, float jw) {
    float ax = fabsf(c);
    float y  = fmaxf(fmaf(ax, -w, w), 0.0f);          // w*(1-|c|), diag-safe
    float s  = sqapx(y);
    float p  = fmaf(fmaf(fmaf(ax, -0.0187293f, 0.0742610f),
                         ax, -0.2121144f), ax, 1.5707288f);   // A&S 4.4.45
    float sg = __uint_as_float((__float_as_uint(c) & 0x80000000u) | 0x3f800000u);
    float q  = fmaf(s, p, nhp);                       // s*p - w*pi/2
    float r  = fmaf(sg, q, -nhp);                     // reflect (+w*pi/2)
    return r * jw;                                    // j-mask
}

__global__ __launch_bounds__(256)
void AngleTensor_69767448756825_kernel(const float* __restrict__ pos,
                                       float* __restrict__ out) {
    const int i    = blockIdx.x;
    const int b    = blockIdx.y;
    const int t    = threadIdx.x;
    const int lane = t & 31;
    const int w    = t >> 5;

    __shared__ float4 su[AT_N];                    // per-k: {x,y,z,w}
    __shared__ __align__(16) u64 su2[AT_N][4];     // per-j: {x,x},{y,y},{z,z},{w,w}

    const float* pb = pos + (size_t)b * AT_N * 3;
    const float pix = pb[i * 3 + 0];
    const float piy = pb[i * 3 + 1];
    const float piz = pb[i * 3 + 2];

    if (t < AT_N) {
        float dx = pb[t * 3 + 0] - pix;
        float dy = pb[t * 3 + 1] - piy;
        float dz = pb[t * 3 + 2] - piz;
        float n2 = dx * dx + dy * dy + dz * dz;
        float inv = (n2 > 0.0f) ? rsqrtf(n2) : 0.0f;   // t==i -> zero vector
        float wt  = (t == i) ? 0.0f : 1.0f;
        float x = dx * inv, y = dy * inv, z = dz * inv;
        su[t] = make_float4(x, y, z, wt);
        su2[t][0] = pk(x, x);
        su2[t][1] = pk(y, y);
        su2[t][2] = pk(z, z);
        su2[t][3] = pk(wt, wt);
    }
    __syncthreads();

    // Lane-owned k-quad: packed xyz for the dot, scalar w/nhp for the epilogue.
    const int k0 = lane << 2;
    const float4 q0 = su[k0 + 0];
    const float4 q1 = su[k0 + 1];
    const float4 q2 = su[k0 + 2];
    const float4 q3 = su[k0 + 3];
    const u64 kx01 = pk(q0.x, q1.x), kx23 = pk(q2.x, q3.x);
    const u64 ky01 = pk(q0.y, q1.y), ky23 = pk(q2.y, q3.y);
    const u64 kz01 = pk(q0.z, q1.z), kz23 = pk(q2.z, q3.z);
    const float w0 = q0.w, w1 = q1.w, w2 = q2.w, w3 = q3.w;
    const float HPI = 1.57079632679f;
    const float n0 = -HPI * w0, n1 = -HPI * w1, n2_ = -HPI * w2, n3 = -HPI * w3;

    float4* orow = reinterpret_cast<float4*>(
        out + ((size_t)b * AT_N + i) * AT_N * AT_N);

    #pragma unroll 2
    for (int it = 0; it < AT_N / 8; ++it) {
        const int j = w * (AT_N / 8) + it;
        const ulonglong2 a0 = reinterpret_cast<const ulonglong2*>(su2[j])[0];
        const ulonglong2 a1 = reinterpret_cast<const ulonglong2*>(su2[j])[1];

        // cos = u_j . u_k  (packed f32x2)
        u64 c01 = fma2(a1.x, kz01, fma2(a0.y, ky01, mul2(a0.x, kx01)));
        u64 c23 = fma2(a1.x, kz23, fma2(a0.y, ky23, mul2(a0.x, kx23)));
        float2 cp01 = upk(c01), cp23 = upk(c23);
        const float jw = upk(a1.y).x;

        float4 r4;
        r4.x = ang(cp01.x, w0, n0,  jw);
        r4.y = ang(cp01.y, w1, n1,  jw);
        r4.z = ang(cp23.x, w2, n2_, jw);
        r4.w = ang(cp23.y, w3, n3,  jw);

        // exact zero on the j==k diagonal
        if ((j >> 2) == lane) {
            switch (j & 3) {
                case 0: r4.x = 0.0f; break;
                case 1: r4.y = 0.0f; break;
                case 2: r4.z = 0.0f; break;
                default: r4.w = 0.0f; break;
            }
        }

        orow[j * (AT_N / 4) + lane] = r4;          // STG.128 coalesced
    }
}

extern "C" void kernel_launch(void* const* d_in, const int* in_sizes, int n_in,
                              void* d_out, int out_size) {
    const int B = out_size / (AT_N * AT_N * AT_N);

    const float* pos = nullptr;
    for (int a = 0; a < n_in; ++a)
        if (in_sizes[a] == B * AT_N * 3) pos = (const float*)d_in[a];
    if (!pos) pos = (const float*)d_in[0];

    dim3 grid(AT_N, B);
    AngleTensor_69767448756825_kernel<<<grid, 256>>>(pos, (float*)d_out);
}